// round 5
// baseline (speedup 1.0000x reference)
#include <cuda_runtime.h>
#include <cuda_fp16.h>
#include <cstdint>

#define NPTS    16384
#define NBINS   256
#define NSLICE  32
#define SLICEN  (NPTS/NSLICE)      // 512 targets per slice
#define TPB     256
#define QPB     256                // queries per block
#define QT      (NPTS/QPB)         // 64 query tiles per direction
#define GRPS    2                  // slice groups per query tile
#define REDA    (2*NPTS/TPB)       // 128
#define XLO     (-8.0f)
#define XWIDTH  (16.0f/NBINS)      // bin width 0.0625

// ---- sort pipeline state (hist/cursor zeroed by k_scan for next replay) ----
__device__ int    g_hist[2][NBINS];
__device__ int    g_start[2][NBINS + 1];
__device__ int    g_cursor[2][NBINS];
__device__ float  g_sxlo[2][NSLICE];
__device__ float  g_sxhi[2][NSLICE];
__device__ float4 g_pts[2][NPTS];        // sorted (x,y,z, orig_idx bits)
__device__ uint4  g_frag[2][NPTS][2];    // target MMA fragments, sorted order
__device__ float  g_part[2][GRPS][NPTS]; // partial min dists, keyed by ORIG index
__device__ float  g_bsum[REDA];

static __device__ __forceinline__ unsigned pkh2(__half lo, __half hi) {
    __half2 h = __halves2half2(lo, hi);
    return *reinterpret_cast<unsigned*>(&h);
}

// m16n8k16 fp16 MMA, fp32 accumulate. A row-major, B col-major.
#define MMA_F16(d0,d1,d2,d3, a0,a1,a2,a3, b0,b1, c0,c1,c2,c3)                       \
    asm("mma.sync.aligned.m16n8k16.row.col.f32.f16.f16.f32 "                        \
        "{%0,%1,%2,%3}, {%4,%5,%6,%7}, {%8,%9}, {%10,%11,%12,%13};"                 \
        : "=f"(d0), "=f"(d1), "=f"(d2), "=f"(d3)                                    \
        : "r"(a0), "r"(a1), "r"(a2), "r"(a3), "r"(b0), "r"(b1),                     \
          "f"(c0), "f"(c1), "f"(c2), "f"(c3))

// ============================================================================
// 1) histogram of x into 256 bins per cloud (fixed clamped range; edge bins
//    get infinite slice ranges later, so clamping never breaks correctness).
// ============================================================================
__global__ void k_hist(const float* __restrict__ adv, const float* __restrict__ ori) {
    int i = blockIdx.x * blockDim.x + threadIdx.x;   // 0 .. 2*NPTS-1
    int c = i >> 14, idx = i & (NPTS - 1);
    const float* src = c ? ori : adv;
    float x = src[3 * idx];
    int bin = (int)((x - XLO) * (1.0f / XWIDTH));
    bin = min(max(bin, 0), NBINS - 1);
    atomicAdd(&g_hist[c][bin], 1);
}

// ============================================================================
// 2) prefix-sum bins, derive conservative x-range per 512-point slice from bin
//    edges, zero hist+cursor for the NEXT graph replay. 1 block, 2 warps.
// ============================================================================
__global__ void k_scan() {
    int lane = threadIdx.x & 31;
    int c    = threadIdx.x >> 5;
    int h[8], s8 = 0;
#pragma unroll
    for (int k = 0; k < 8; k++) { h[k] = g_hist[c][lane * 8 + k]; s8 += h[k]; }
    int incl = s8;
#pragma unroll
    for (int off = 1; off < 32; off <<= 1) {
        int v = __shfl_up_sync(0xffffffffu, incl, off);
        if (lane >= off) incl += v;
    }
    int run = incl - s8;
#pragma unroll
    for (int k = 0; k < 8; k++) { g_start[c][lane * 8 + k] = run; run += h[k]; }
    if (lane == 31) g_start[c][NBINS] = run;   // == NPTS
    __syncthreads();

    int s = lane;                 // one slice per lane
    int pos0 = s * SLICEN, pos1 = pos0 + SLICEN;
    int b0 = 0;
    while (b0 < NBINS - 1 && g_start[c][b0 + 1] <= pos0) b0++;
    int b1 = b0;
    while (b1 < NBINS - 1 && g_start[c][b1 + 1] < pos1) b1++;
    g_sxlo[c][s] = (b0 == 0)         ? __int_as_float(0xFF800000) : XLO + b0 * XWIDTH;
    g_sxhi[c][s] = (b1 == NBINS - 1) ? __int_as_float(0x7F800000) : XLO + (b1 + 1) * XWIDTH;

#pragma unroll
    for (int k = 0; k < 8; k++) {
        g_hist[c][lane * 8 + k]   = 0;
        g_cursor[c][lane * 8 + k] = 0;
    }
}

// ============================================================================
// 3) counting-sort scatter: sorted points + prebuilt fp16-split B fragments.
//    B k-slots: (txh,tyh, tzh,txh, tyh,tzh, txl,tyl, tzl,tqh, tql,0 ...)
//    where tqh+tql = fp16 split of -|t|^2/2 (A supplies 1.0 at k9,k10).
// ============================================================================
__global__ void k_scatter(const float* __restrict__ adv, const float* __restrict__ ori) {
    int i = blockIdx.x * blockDim.x + threadIdx.x;
    int c = i >> 14, idx = i & (NPTS - 1);
    const float* src = c ? ori : adv;
    float x = src[3 * idx], y = src[3 * idx + 1], z = src[3 * idx + 2];
    int bin = (int)((x - XLO) * (1.0f / XWIDTH));
    bin = min(max(bin, 0), NBINS - 1);
    int pos = g_start[c][bin] + atomicAdd(&g_cursor[c][bin], 1);

    g_pts[c][pos] = make_float4(x, y, z, __int_as_float(idx));

    __half xh = __float2half_rn(x), yh = __float2half_rn(y), zh = __float2half_rn(z);
    __half xl = __float2half_rn(x - __half2float(xh));
    __half yl = __float2half_rn(y - __half2float(yh));
    __half zl = __float2half_rn(z - __half2float(zh));
    float th = -0.5f * (x * x + y * y + z * z);
    __half tqh = __float2half_rn(th);
    __half tql = __float2half_rn(th - __half2float(tqh));
    __half hz  = __float2half_rn(0.f);
    unsigned Q0 = pkh2(xh, yh), Q1 = pkh2(zh, xh), Q2 = pkh2(yh, zh);
    unsigned Q3 = pkh2(xl, yl), Q4 = pkh2(zl, tqh), Q5 = pkh2(tql, hz);
    // interleaved pair layout {Q0,Q4, Q1,Q5, Q2,Q6, Q3,Q7}
    g_frag[c][pos][0] = make_uint4(Q0, Q4, Q1, Q5);
    g_frag[c][pos][1] = make_uint4(Q2, 0u, Q3, 0u);
}

// ============================================================================
// 4) pruned MMA sweep. Block = (dir, 256-query tile, group). Warp owns 32
//    x-adjacent queries; processes home slice, then outward slices (alternating
//    deltas per group), skipping slices with x-gap^2 > warp bound.
// ============================================================================
__global__ void __launch_bounds__(TPB)
k_main() {
    __shared__ unsigned qA[QPB][8];
    __shared__ float sQsq[QPB], sQx[QPB];
    __shared__ int   sQid[QPB];

    int b   = blockIdx.x;
    int dir = b / (QT * GRPS);
    int rem = b % (QT * GRPS);
    int qt  = rem / GRPS;
    int grp = rem % GRPS;
    int qc  = dir;          // dir0: queries = adv(cloud0), targets = ori(cloud1)
    int tc  = 1 - dir;
    int tid = threadIdx.x;

    // ---- stage query fragments from sorted points ----
    {
        float4 p = g_pts[qc][qt * QPB + tid];
        float x = p.x, y = p.y, z = p.z;
        __half xh = __float2half_rn(x), yh = __float2half_rn(y), zh = __float2half_rn(z);
        __half xl = __float2half_rn(x - __half2float(xh));
        __half yl = __float2half_rn(y - __half2float(yh));
        __half zl = __float2half_rn(z - __half2float(zh));
        __half one = __float2half_rn(1.f), hz = __float2half_rn(0.f);
        // A pairs {P0,P4, P1,P5, P2,P6, P3,P7}:
        qA[tid][0] = pkh2(xh, yh);    // P0 (k0,k1)
        qA[tid][1] = pkh2(zh, one);   // P4 (k8,k9)
        qA[tid][2] = pkh2(zh, xl);    // P1 (k2,k3)
        qA[tid][3] = pkh2(one, hz);   // P5 (k10,k11)
        qA[tid][4] = pkh2(yl, zl);    // P2 (k4,k5)
        qA[tid][5] = 0u;              // P6
        qA[tid][6] = pkh2(xh, yh);    // P3 (k6,k7)
        qA[tid][7] = 0u;              // P7
        sQsq[tid] = x * x + y * y + z * z;
        sQx[tid]  = x;
        sQid[tid] = __float_as_int(p.w);
    }
    __syncthreads();

    int lane = tid & 31;
    int warp = tid >> 5;
    int gid  = lane >> 2;
    int tl   = lane & 3;
    int lr   = warp * 32 + gid;

    uint2 u0 = *reinterpret_cast<const uint2*>(&qA[lr +  0][2 * tl]);
    uint2 u1 = *reinterpret_cast<const uint2*>(&qA[lr +  8][2 * tl]);
    uint2 u2 = *reinterpret_cast<const uint2*>(&qA[lr + 16][2 * tl]);
    uint2 u3 = *reinterpret_cast<const uint2*>(&qA[lr + 24][2 * tl]);
    unsigned a00 = u0.x, a01 = u1.x, a02 = u0.y, a03 = u1.y;
    unsigned a10 = u2.x, a11 = u3.x, a12 = u2.y, a13 = u3.y;

    float q0 = sQsq[lr], q1 = sQsq[lr + 8], q2 = sQsq[lr + 16], q3 = sQsq[lr + 24];

    // warp x-range
    float xa = sQx[lr], xb = sQx[lr + 8], xc = sQx[lr + 16], xd = sQx[lr + 24];
    float wlo = fminf(fminf(xa, xb), fminf(xc, xd));
    float whi = fmaxf(fmaxf(xa, xb), fmaxf(xc, xd));
#pragma unroll
    for (int off = 16; off >= 1; off >>= 1) {
        wlo = fminf(wlo, __shfl_xor_sync(0xffffffffu, wlo, off));
        whi = fmaxf(whi, __shfl_xor_sync(0xffffffffu, whi, off));
    }

    float ninf = __int_as_float(0xFF800000);
    float mx00 = ninf, mx01 = ninf, mx10 = ninf, mx11 = ninf;
    const float zf = 0.0f;

    const uint2* fb = reinterpret_cast<const uint2*>(&g_frag[tc][0][0]);
    int home = qt >> 1;   // QT/NSLICE = 2

    for (int step = 0; step < NSLICE; step++) {
        int s;
        if (step == 0) {
            s = home;
        } else {
            int d = ((step & 1) ^ grp) ? step : -step;
            s = home + d;
            if (s < 0 || s >= NSLICE) continue;
            // warp bound = max over queries of current best dist
            float bnd = fmaxf(fmaxf(fmaf(-2.f, mx00, q0), fmaf(-2.f, mx01, q1)),
                              fmaxf(fmaf(-2.f, mx10, q2), fmaf(-2.f, mx11, q3)));
#pragma unroll
            for (int off = 16; off >= 1; off >>= 1)
                bnd = fmaxf(bnd, __shfl_xor_sync(0xffffffffu, bnd, off));
            float lo = g_sxlo[tc][s], hi = g_sxhi[tc][s];
            float gap = fmaxf(0.f, fmaxf(lo - whi, wlo - hi));
            if (gap * gap > bnd + 1e-4f) continue;   // provably cannot improve
        }
        int tb = s * SLICEN;
#pragma unroll 4
        for (int j = 0; j < SLICEN; j += 8) {
            uint2 bb = fb[(tb + j + gid) * 4 + tl];
            float d0, d1, d2, d3;
            MMA_F16(d0, d1, d2, d3, a00, a01, a02, a03, bb.x, bb.y, zf, zf, zf, zf);
            mx00 = fmaxf(mx00, fmaxf(d0, d1));
            mx01 = fmaxf(mx01, fmaxf(d2, d3));
            MMA_F16(d0, d1, d2, d3, a10, a11, a12, a13, bb.x, bb.y, zf, zf, zf, zf);
            mx10 = fmaxf(mx10, fmaxf(d0, d1));
            mx11 = fmaxf(mx11, fmaxf(d2, d3));
        }
    }

    // fold the 4 tl-lanes per row, write partials keyed by ORIGINAL index
#pragma unroll
    for (int off = 1; off <= 2; off <<= 1) {
        mx00 = fmaxf(mx00, __shfl_xor_sync(0xffffffffu, mx00, off));
        mx01 = fmaxf(mx01, __shfl_xor_sync(0xffffffffu, mx01, off));
        mx10 = fmaxf(mx10, __shfl_xor_sync(0xffffffffu, mx10, off));
        mx11 = fmaxf(mx11, __shfl_xor_sync(0xffffffffu, mx11, off));
    }
    if (tl == 0) {
        g_part[dir][grp][sQid[lr +  0]] = fmaf(-2.f, mx00, q0);
        g_part[dir][grp][sQid[lr +  8]] = fmaf(-2.f, mx01, q1);
        g_part[dir][grp][sQid[lr + 16]] = fmaf(-2.f, mx10, q2);
        g_part[dir][grp][sQid[lr + 24]] = fmaf(-2.f, mx11, q3);
    }
}

// ============================================================================
// 5) reductions: min over groups per row (orig-index order -> deterministic),
//    then sum to the chamfer scalar.
// ============================================================================
__global__ void __launch_bounds__(TPB)
k_red_a() {
    __shared__ float sh[TPB];
    int rid = blockIdx.x * TPB + threadIdx.x;
    int dir = rid >> 14;
    int row = rid & (NPTS - 1);
    float v = fminf(g_part[dir][0][row], g_part[dir][1][row]);
    sh[threadIdx.x] = v;
    __syncthreads();
    for (int k = TPB / 2; k > 0; k >>= 1) {
        if (threadIdx.x < k) sh[threadIdx.x] += sh[threadIdx.x + k];
        __syncthreads();
    }
    if (threadIdx.x == 0) g_bsum[blockIdx.x] = sh[0];
}

__global__ void k_red_b(float* __restrict__ out) {
    __shared__ float sh[REDA];
    sh[threadIdx.x] = g_bsum[threadIdx.x];
    __syncthreads();
    for (int k = REDA / 2; k > 0; k >>= 1) {
        if (threadIdx.x < k) sh[threadIdx.x] += sh[threadIdx.x + k];
        __syncthreads();
    }
    if (threadIdx.x == 0) out[0] = sh[0] / (float)NPTS;
}

extern "C" void kernel_launch(void* const* d_in, const int* in_sizes, int n_in,
                              void* d_out, int out_size) {
    const float* adv = (const float*)d_in[0];
    const float* ori = (const float*)d_in[1];
    k_hist<<<2 * NPTS / 256, 256>>>(adv, ori);
    k_scan<<<1, 64>>>();
    k_scatter<<<2 * NPTS / 256, 256>>>(adv, ori);
    k_main<<<2 * QT * GRPS, TPB>>>();
    k_red_a<<<REDA, TPB>>>();
    k_red_b<<<1, REDA>>>((float*)d_out);
}

// round 6
// speedup vs baseline: 1.9662x; 1.9662x over previous
#include <cuda_runtime.h>
#include <cuda_fp16.h>
#include <cstdint>

#define NPTS    16384
#define NBINS   256
#define NSLICE  16
#define SLICEN  (NPTS/NSLICE)      // 1024 targets per slice
#define TPB     256
#define QPB     256                // queries per tile
#define QT      (NPTS/QPB)         // 64 tiles per direction
#define WPB     8                  // warps per block
#define REDA    (2*NPTS/TPB)       // 128
#define XLO     (-8.0f)
#define XWIDTH  (16.0f/NBINS)

// ---- pipeline state (hist/cursor re-zeroed by k_scan for next graph replay) ----
__device__ int    g_hist[2][NBINS];
__device__ int    g_start[2][NBINS + 1];
__device__ int    g_cursor[2][NBINS];
__device__ float  g_sxlo[2][NSLICE], g_sxhi[2][NSLICE];  // exact slice x-ranges
__device__ float4 g_pts[2][NPTS];          // sorted (x,y,z, orig_idx bits)
__device__ uint4  g_frag[2][NPTS][2];      // target B-fragments, sorted order
__device__ float  g_seed[2][NPTS];         // home-slice best, keyed by ORIG idx
__device__ float  g_wb[2][QT][WPB];        // per-warp bound (max seed dist)
__device__ float  g_wlo[2][QT][WPB], g_whi[2][QT][WPB];  // per-warp query x-range
__device__ float  g_part[2][NSLICE][NPTS]; // per-slice partials, ORIG idx keyed
__device__ float  g_bsum[REDA];

static __device__ __forceinline__ unsigned pkh2(__half lo, __half hi) {
    __half2 h = __halves2half2(lo, hi);
    return *reinterpret_cast<unsigned*>(&h);
}

// m16n8k16 fp16 MMA, fp32 accumulate. A row-major, B col-major.
#define MMA_F16(d0,d1,d2,d3, a0,a1,a2,a3, b0,b1, c0,c1,c2,c3)                       \
    asm("mma.sync.aligned.m16n8k16.row.col.f32.f16.f16.f32 "                        \
        "{%0,%1,%2,%3}, {%4,%5,%6,%7}, {%8,%9}, {%10,%11,%12,%13};"                 \
        : "=f"(d0), "=f"(d1), "=f"(d2), "=f"(d3)                                    \
        : "r"(a0), "r"(a1), "r"(a2), "r"(a3), "r"(b0), "r"(b1),                     \
          "f"(c0), "f"(c1), "f"(c2), "f"(c3))

// ============================================================================
// 1) x-histogram (256 bins per cloud, clamped; srange makes ranges exact later)
// ============================================================================
__global__ void k_hist(const float* __restrict__ adv, const float* __restrict__ ori) {
    int i = blockIdx.x * blockDim.x + threadIdx.x;
    int c = i >> 14, idx = i & (NPTS - 1);
    const float* src = c ? ori : adv;
    float x = src[3 * idx];
    int bin = min(max((int)((x - XLO) * (1.0f / XWIDTH)), 0), NBINS - 1);
    atomicAdd(&g_hist[c][bin], 1);
}

// ============================================================================
// 2) prefix-sum bins; zero hist+cursor for the next replay. 1 block, 2 warps.
// ============================================================================
__global__ void k_scan() {
    int lane = threadIdx.x & 31;
    int c    = threadIdx.x >> 5;
    int h[8], s8 = 0;
#pragma unroll
    for (int k = 0; k < 8; k++) { h[k] = g_hist[c][lane * 8 + k]; s8 += h[k]; }
    int incl = s8;
#pragma unroll
    for (int off = 1; off < 32; off <<= 1) {
        int v = __shfl_up_sync(0xffffffffu, incl, off);
        if (lane >= off) incl += v;
    }
    int run = incl - s8;
#pragma unroll
    for (int k = 0; k < 8; k++) { g_start[c][lane * 8 + k] = run; run += h[k]; }
    if (lane == 31) g_start[c][NBINS] = run;
#pragma unroll
    for (int k = 0; k < 8; k++) {
        g_hist[c][lane * 8 + k]   = 0;
        g_cursor[c][lane * 8 + k] = 0;
    }
}

// ============================================================================
// 3) counting-sort scatter: sorted points + fp16-split B fragments.
//    B k-slots: (xh,yh,zh, xh,yh,zh, xl,yl,zl, tqh,tql,0...), tq = -|t|^2/2.
// ============================================================================
__global__ void k_scatter(const float* __restrict__ adv, const float* __restrict__ ori) {
    int i = blockIdx.x * blockDim.x + threadIdx.x;
    int c = i >> 14, idx = i & (NPTS - 1);
    const float* src = c ? ori : adv;
    float x = src[3 * idx], y = src[3 * idx + 1], z = src[3 * idx + 2];
    int bin = min(max((int)((x - XLO) * (1.0f / XWIDTH)), 0), NBINS - 1);
    int pos = g_start[c][bin] + atomicAdd(&g_cursor[c][bin], 1);

    g_pts[c][pos] = make_float4(x, y, z, __int_as_float(idx));

    __half xh = __float2half_rn(x), yh = __float2half_rn(y), zh = __float2half_rn(z);
    __half xl = __float2half_rn(x - __half2float(xh));
    __half yl = __float2half_rn(y - __half2float(yh));
    __half zl = __float2half_rn(z - __half2float(zh));
    float tq = -0.5f * (x * x + y * y + z * z);
    __half tqh = __float2half_rn(tq);
    __half tql = __float2half_rn(tq - __half2float(tqh));
    __half hz  = __float2half_rn(0.f);
    unsigned Q0 = pkh2(xh, yh), Q1 = pkh2(zh, xh), Q2 = pkh2(yh, zh);
    unsigned Q3 = pkh2(xl, yl), Q4 = pkh2(zl, tqh), Q5 = pkh2(tql, hz);
    g_frag[c][pos][0] = make_uint4(Q0, Q4, Q1, Q5);   // {Q0,Q4, Q1,Q5, ...}
    g_frag[c][pos][1] = make_uint4(Q2, 0u, Q3, 0u);
}

// ============================================================================
// 4) exact slice x-ranges from sorted points (32 blocks = cloud x slice).
// ============================================================================
__global__ void __launch_bounds__(TPB)
k_srange() {
    __shared__ float slo[WPB], shi[WPB];
    int c = blockIdx.x >> 4, s = blockIdx.x & 15;
    float lo = __int_as_float(0x7F800000), hi = -lo;
#pragma unroll
    for (int k = 0; k < 4; k++) {
        float x = g_pts[c][s * SLICEN + threadIdx.x + k * TPB].x;
        lo = fminf(lo, x); hi = fmaxf(hi, x);
    }
#pragma unroll
    for (int off = 16; off >= 1; off >>= 1) {
        lo = fminf(lo, __shfl_xor_sync(0xffffffffu, lo, off));
        hi = fmaxf(hi, __shfl_xor_sync(0xffffffffu, hi, off));
    }
    int w = threadIdx.x >> 5;
    if ((threadIdx.x & 31) == 0) { slo[w] = lo; shi[w] = hi; }
    __syncthreads();
    if (threadIdx.x == 0) {
        for (int k = 1; k < WPB; k++) { lo = fminf(lo, slo[k]); hi = fmaxf(hi, shi[k]); }
        g_sxlo[c][s] = lo; g_sxhi[c][s] = hi;
    }
}

// ---- shared inner-sweep helper: stage queries into qA/sQsq/sQx/sQid ----
static __device__ __forceinline__ void stage_query(
    int qc, int row, int tid, unsigned (*qA)[8], float* sQsq, float* sQx, int* sQid) {
    float4 p = g_pts[qc][row];
    float x = p.x, y = p.y, z = p.z;
    __half xh = __float2half_rn(x), yh = __float2half_rn(y), zh = __float2half_rn(z);
    __half xl = __float2half_rn(x - __half2float(xh));
    __half yl = __float2half_rn(y - __half2float(yh));
    __half zl = __float2half_rn(z - __half2float(zh));
    __half one = __float2half_rn(1.f), hz = __float2half_rn(0.f);
    qA[tid][0] = pkh2(xh, yh);  qA[tid][1] = pkh2(zh, one);
    qA[tid][2] = pkh2(zh, xl);  qA[tid][3] = pkh2(one, hz);
    qA[tid][4] = pkh2(yl, zl);  qA[tid][5] = 0u;
    qA[tid][6] = pkh2(xh, yh);  qA[tid][7] = 0u;
    sQsq[tid] = x * x + y * y + z * z;
    sQx[tid]  = x;
    sQid[tid] = __float_as_int(p.w);
}

// ============================================================================
// 5) seed: block = (dir, qt). Sweep the HOME slice only; write seed dists
//    (orig-idx keyed) + per-warp bound and query x-range.
// ============================================================================
__global__ void __launch_bounds__(TPB)
k_seed() {
    __shared__ uint4    sB4[SLICEN * 2];   // 32 KB
    __shared__ unsigned qA[QPB][8];        // 8 KB
    __shared__ float    sQsq[QPB], sQx[QPB];
    __shared__ int      sQid[QPB];

    int b = blockIdx.x, dir = b / QT, qt = b % QT;
    int qc = dir, tc = 1 - dir;
    int tid = threadIdx.x;
    int home = qt >> 2, tb = home * SLICEN;

    stage_query(qc, qt * QPB + tid, tid, qA, sQsq, sQx, sQid);
    for (int k = tid; k < SLICEN * 2; k += TPB) sB4[k] = g_frag[tc][tb + (k >> 1)][k & 1];
    __syncthreads();

    int lane = tid & 31, warp = tid >> 5;
    int gid = lane >> 2, tl = lane & 3;
    int lr = warp * 32 + gid;

    uint2 u0 = *reinterpret_cast<const uint2*>(&qA[lr +  0][2 * tl]);
    uint2 u1 = *reinterpret_cast<const uint2*>(&qA[lr +  8][2 * tl]);
    uint2 u2 = *reinterpret_cast<const uint2*>(&qA[lr + 16][2 * tl]);
    uint2 u3 = *reinterpret_cast<const uint2*>(&qA[lr + 24][2 * tl]);
    unsigned a00 = u0.x, a01 = u1.x, a02 = u0.y, a03 = u1.y;
    unsigned a10 = u2.x, a11 = u3.x, a12 = u2.y, a13 = u3.y;

    float ninf = __int_as_float(0xFF800000);
    float mx00 = ninf, mx01 = ninf, mx10 = ninf, mx11 = ninf;
    const float zf = 0.0f;
    const uint2* sb = reinterpret_cast<const uint2*>(sB4);

#pragma unroll 4
    for (int j = 0; j < SLICEN; j += 8) {
        uint2 bb = sb[(j + gid) * 4 + tl];
        float d0, d1, d2, d3;
        MMA_F16(d0, d1, d2, d3, a00, a01, a02, a03, bb.x, bb.y, zf, zf, zf, zf);
        mx00 = fmaxf(mx00, fmaxf(d0, d1));
        mx01 = fmaxf(mx01, fmaxf(d2, d3));
        MMA_F16(d0, d1, d2, d3, a10, a11, a12, a13, bb.x, bb.y, zf, zf, zf, zf);
        mx10 = fmaxf(mx10, fmaxf(d0, d1));
        mx11 = fmaxf(mx11, fmaxf(d2, d3));
    }
#pragma unroll
    for (int off = 1; off <= 2; off <<= 1) {
        mx00 = fmaxf(mx00, __shfl_xor_sync(0xffffffffu, mx00, off));
        mx01 = fmaxf(mx01, __shfl_xor_sync(0xffffffffu, mx01, off));
        mx10 = fmaxf(mx10, __shfl_xor_sync(0xffffffffu, mx10, off));
        mx11 = fmaxf(mx11, __shfl_xor_sync(0xffffffffu, mx11, off));
    }
    float d0 = fmaf(-2.f, mx00, sQsq[lr +  0]);
    float d1 = fmaf(-2.f, mx01, sQsq[lr +  8]);
    float d2 = fmaf(-2.f, mx10, sQsq[lr + 16]);
    float d3 = fmaf(-2.f, mx11, sQsq[lr + 24]);
    if (tl == 0) {
        g_seed[dir][sQid[lr +  0]] = d0;
        g_seed[dir][sQid[lr +  8]] = d1;
        g_seed[dir][sQid[lr + 16]] = d2;
        g_seed[dir][sQid[lr + 24]] = d3;
    }
    // per-warp bound and x-range
    float bnd = fmaxf(fmaxf(d0, d1), fmaxf(d2, d3));
    float xlo = fminf(fminf(sQx[lr], sQx[lr + 8]), fminf(sQx[lr + 16], sQx[lr + 24]));
    float xhi = fmaxf(fmaxf(sQx[lr], sQx[lr + 8]), fmaxf(sQx[lr + 16], sQx[lr + 24]));
#pragma unroll
    for (int off = 16; off >= 1; off >>= 1) {
        bnd = fmaxf(bnd, __shfl_xor_sync(0xffffffffu, bnd, off));
        xlo = fminf(xlo, __shfl_xor_sync(0xffffffffu, xlo, off));
        xhi = fmaxf(xhi, __shfl_xor_sync(0xffffffffu, xhi, off));
    }
    if (lane == 0) {
        g_wb [dir][qt][warp] = bnd;
        g_wlo[dir][qt][warp] = xlo;
        g_whi[dir][qt][warp] = xhi;
    }
}

// ============================================================================
// 6) sweep: block = (dir, qt, sp). Per-warp prune via x-gap vs seed bound;
//    all-pruned blocks exit before staging. Unpruned warps sweep the slice.
// ============================================================================
__global__ void __launch_bounds__(TPB)
k_sweep() {
    __shared__ uint4    sB4[SLICEN * 2];
    __shared__ unsigned qA[QPB][8];
    __shared__ float    sQsq[QPB], sQx[QPB];
    __shared__ int      sQid[QPB];

    int b = blockIdx.x;
    int dir = b / (QT * NSLICE);
    int rem = b % (QT * NSLICE);
    int qt = rem / NSLICE, sp = rem % NSLICE;
    int qc = dir, tc = 1 - dir;
    int tid = threadIdx.x;
    int lane = tid & 31, warp = tid >> 5;
    int home = qt >> 2;
    const float inf = __int_as_float(0x7F800000);

    // per-warp prune decision (uniform within warp)
    int pruned;
    if (sp == home) {
        pruned = 1;   // seed already covered it
    } else {
        float wb  = g_wb [dir][qt][warp];
        float wlo = g_wlo[dir][qt][warp];
        float whi = g_whi[dir][qt][warp];
        float gap = fmaxf(0.f, fmaxf(g_sxlo[tc][sp] - whi, wlo - g_sxhi[tc][sp]));
        pruned = (gap * gap > wb + 1e-3f);
    }
    if (__syncthreads_and(pruned)) {
        // whole block pruned: fill partials with +inf (one row per thread)
        int orig = __float_as_int(g_pts[qc][qt * QPB + tid].w);
        g_part[dir][sp][orig] = inf;
        return;
    }

    stage_query(qc, qt * QPB + tid, tid, qA, sQsq, sQx, sQid);
    {
        int tb = sp * SLICEN;
        for (int k = tid; k < SLICEN * 2; k += TPB) sB4[k] = g_frag[tc][tb + (k >> 1)][k & 1];
    }
    __syncthreads();

    if (pruned) {   // this warp only: write inf for its 32 rows
        g_part[dir][sp][sQid[warp * 32 + lane]] = inf;
        return;
    }

    int gid = lane >> 2, tl = lane & 3;
    int lr = warp * 32 + gid;
    uint2 u0 = *reinterpret_cast<const uint2*>(&qA[lr +  0][2 * tl]);
    uint2 u1 = *reinterpret_cast<const uint2*>(&qA[lr +  8][2 * tl]);
    uint2 u2 = *reinterpret_cast<const uint2*>(&qA[lr + 16][2 * tl]);
    uint2 u3 = *reinterpret_cast<const uint2*>(&qA[lr + 24][2 * tl]);
    unsigned a00 = u0.x, a01 = u1.x, a02 = u0.y, a03 = u1.y;
    unsigned a10 = u2.x, a11 = u3.x, a12 = u2.y, a13 = u3.y;

    float ninf = __int_as_float(0xFF800000);
    float mx00 = ninf, mx01 = ninf, mx10 = ninf, mx11 = ninf;
    const float zf = 0.0f;
    const uint2* sb = reinterpret_cast<const uint2*>(sB4);

#pragma unroll 4
    for (int j = 0; j < SLICEN; j += 8) {
        uint2 bb = sb[(j + gid) * 4 + tl];
        float d0, d1, d2, d3;
        MMA_F16(d0, d1, d2, d3, a00, a01, a02, a03, bb.x, bb.y, zf, zf, zf, zf);
        mx00 = fmaxf(mx00, fmaxf(d0, d1));
        mx01 = fmaxf(mx01, fmaxf(d2, d3));
        MMA_F16(d0, d1, d2, d3, a10, a11, a12, a13, bb.x, bb.y, zf, zf, zf, zf);
        mx10 = fmaxf(mx10, fmaxf(d0, d1));
        mx11 = fmaxf(mx11, fmaxf(d2, d3));
    }
#pragma unroll
    for (int off = 1; off <= 2; off <<= 1) {
        mx00 = fmaxf(mx00, __shfl_xor_sync(0xffffffffu, mx00, off));
        mx01 = fmaxf(mx01, __shfl_xor_sync(0xffffffffu, mx01, off));
        mx10 = fmaxf(mx10, __shfl_xor_sync(0xffffffffu, mx10, off));
        mx11 = fmaxf(mx11, __shfl_xor_sync(0xffffffffu, mx11, off));
    }
    if (tl == 0) {
        g_part[dir][sp][sQid[lr +  0]] = fmaf(-2.f, mx00, sQsq[lr +  0]);
        g_part[dir][sp][sQid[lr +  8]] = fmaf(-2.f, mx01, sQsq[lr +  8]);
        g_part[dir][sp][sQid[lr + 16]] = fmaf(-2.f, mx10, sQsq[lr + 16]);
        g_part[dir][sp][sQid[lr + 24]] = fmaf(-2.f, mx11, sQsq[lr + 24]);
    }
}

// ============================================================================
// 7) reductions (orig-index order -> deterministic summation)
// ============================================================================
__global__ void __launch_bounds__(TPB)
k_red_a() {
    __shared__ float sh[TPB];
    int rid = blockIdx.x * TPB + threadIdx.x;
    int dir = rid >> 14, row = rid & (NPTS - 1);
    float v = g_seed[dir][row];
#pragma unroll
    for (int sp = 0; sp < NSLICE; sp++) v = fminf(v, g_part[dir][sp][row]);
    sh[threadIdx.x] = v;
    __syncthreads();
    for (int k = TPB / 2; k > 0; k >>= 1) {
        if (threadIdx.x < k) sh[threadIdx.x] += sh[threadIdx.x + k];
        __syncthreads();
    }
    if (threadIdx.x == 0) g_bsum[blockIdx.x] = sh[0];
}

__global__ void k_red_b(float* __restrict__ out) {
    __shared__ float sh[REDA];
    sh[threadIdx.x] = g_bsum[threadIdx.x];
    __syncthreads();
    for (int k = REDA / 2; k > 0; k >>= 1) {
        if (threadIdx.x < k) sh[threadIdx.x] += sh[threadIdx.x + k];
        __syncthreads();
    }
    if (threadIdx.x == 0) out[0] = sh[0] / (float)NPTS;
}

extern "C" void kernel_launch(void* const* d_in, const int* in_sizes, int n_in,
                              void* d_out, int out_size) {
    const float* adv = (const float*)d_in[0];
    const float* ori = (const float*)d_in[1];
    k_hist<<<2 * NPTS / 256, 256>>>(adv, ori);
    k_scan<<<1, 64>>>();
    k_scatter<<<2 * NPTS / 256, 256>>>(adv, ori);
    k_srange<<<2 * NSLICE, TPB>>>();
    k_seed<<<2 * QT, TPB>>>();
    k_sweep<<<2 * QT * NSLICE, TPB>>>();
    k_red_a<<<REDA, TPB>>>();
    k_red_b<<<1, REDA>>>((float*)d_out);
}